// round 17
// baseline (speedup 1.0000x reference)
#include <cuda_runtime.h>
#include <cuda_fp16.h>
#include <cstdint>

#define NMAX 100000
#define HH   128
#define KS2  136          // padded row stride (half elems) for K=128 tiles

// Per-node projections (fp16). [node][256]: cols 0..127 = z@W1a (left/src),
// cols 128..255 = z@W1b + b1 (right/dst, bias folded).
__device__ __half g_P[(size_t)NMAX * 256];
__device__ __half g_O[(size_t)NMAX * 256];

// Pre-built B' image: [n(256 output cols)][KS2] fp16 (w1 transposed, fp16).
__device__ __align__(16) __half g_Bimg[256 * KS2];

// ---------------- helpers ----------------
__device__ __forceinline__ uint32_t smem_u32(const void* p) {
    uint32_t a;
    asm("{ .reg .u64 t; cvta.to.shared.u64 t, %1; cvt.u32.u64 %0, t; }"
        : "=r"(a) : "l"(p));
    return a;
}

__device__ __forceinline__ void ldsm_x4(uint32_t* r, uint32_t addr) {
    asm volatile("ldmatrix.sync.aligned.m8n8.x4.shared.b16 {%0,%1,%2,%3}, [%4];\n"
                 : "=r"(r[0]), "=r"(r[1]), "=r"(r[2]), "=r"(r[3]) : "r"(addr));
}

__device__ __forceinline__ void mma_f16(float* c, const uint32_t* a,
                                        uint32_t b0, uint32_t b1) {
    asm volatile(
        "mma.sync.aligned.m16n8k16.row.col.f32.f16.f16.f32 "
        "{%0,%1,%2,%3}, {%4,%5,%6,%7}, {%8,%9}, {%0,%1,%2,%3};\n"
        : "+f"(c[0]), "+f"(c[1]), "+f"(c[2]), "+f"(c[3])
        : "r"(a[0]), "r"(a[1]), "r"(a[2]), "r"(a[3]), "r"(b0), "r"(b1));
}

// ---------------- prep: build B' image once ----------------
__global__ void prep_B(const float* __restrict__ w1) {
    int i = blockIdx.x * blockDim.x + threadIdx.x;   // over 256*128
    if (i >= 256 * 128) return;
    int nn = i >> 7;            // output col 0..255
    int k = i & 127;
    int cb = nn >> 7;
    int nloc = nn & 127;
    g_Bimg[(size_t)nn * KS2 + k] = __float2half_rn(w1[(cb * 128 + k) * 128 + nloc]);
}

// ---------------- GEMM (exact R9 winner): C[128][256] per CTA ----------------
__global__ __launch_bounds__(256, 2)
void gemm_mma(const float* __restrict__ Zp, const float* __restrict__ Zo,
              const float* __restrict__ b1, int n) {
    extern __shared__ __half smem[];
    __half* As = smem;                       // [128][KS2]
    __half* Bs[2] = { smem + 128 * KS2,      // [64][KS2] buf0
                      smem + 192 * KS2 };    // [64][KS2] buf1

    const int tid = threadIdx.x;
    const int lane = tid & 31;
    const int wid = tid >> 5;
    const int wm = wid & 3;
    const int wn = wid >> 2;

    const float* A = blockIdx.y ? Zo : Zp;
    __half* C = blockIdx.y ? g_O : g_P;
    const long rowBase = (long)blockIdx.x * 128;

    auto cpchunk = [&](int c, __half* dst) {
        const __half* src = g_Bimg + (size_t)c * 64 * KS2;
        uint32_t d = smem_u32(dst);
        for (int i = tid; i < 64 * KS2 / 8; i += 256)
            asm volatile("cp.async.cg.shared.global [%0], [%1], 16;\n"
                         :: "r"(d + i * 16), "l"(src + i * 8) : "memory");
    };

    cpchunk(0, Bs[0]);
    asm volatile("cp.async.commit_group;\n" ::: "memory");
    cpchunk(1, Bs[1]);
    asm volatile("cp.async.commit_group;\n" ::: "memory");

    {
        int row = tid >> 1;
        int half = tid & 1;
        long grow = rowBase + row;
        const float* ap = A + grow * HH + half * 64;
        __half* as = As + row * KS2 + half * 64;
        #pragma unroll
        for (int j = 0; j < 16; j++) {
            float4 v = (grow < n) ? reinterpret_cast<const float4*>(ap)[j]
                                  : make_float4(0.f, 0.f, 0.f, 0.f);
            __half2 h0 = __floats2half2_rn(v.x, v.y);
            __half2 h1 = __floats2half2_rn(v.z, v.w);
            uint2 hh;
            hh.x = *reinterpret_cast<uint32_t*>(&h0);
            hh.y = *reinterpret_cast<uint32_t*>(&h1);
            *reinterpret_cast<uint2*>(as + j * 4) = hh;
        }
    }

    asm volatile("cp.async.wait_group 1;\n" ::: "memory");
    __syncthreads();

    const uint32_t sbA = smem_u32(As);
    const uint32_t sbB[2] = { smem_u32(Bs[0]), smem_u32(Bs[1]) };
    uint32_t a_base[2], b_off[2];
    #pragma unroll
    for (int tm = 0; tm < 2; tm++)
        a_base[tm] = sbA + ((wm * 32 + tm * 16 + (lane & 15)) * KS2
                            + (lane >> 4) * 8) * 2;
    #pragma unroll
    for (int np = 0; np < 2; np++)
        b_off[np] = ((wn * 32 + np * 16 + ((lane >> 4) << 3) + (lane & 7)) * KS2
                      + ((lane >> 3) & 1) * 8) * 2;

    for (int c = 0; c < 4; c++) {
        const uint32_t bb = sbB[c & 1];
        float acc[2][4][4];
        #pragma unroll
        for (int tm = 0; tm < 2; tm++)
            #pragma unroll
            for (int tn = 0; tn < 4; tn++)
                #pragma unroll
                for (int q = 0; q < 4; q++) acc[tm][tn][q] = 0.f;

        #pragma unroll 2
        for (int ks = 0; ks < 8; ks++) {
            uint32_t a[2][4], b[2][4];
            #pragma unroll
            for (int tm = 0; tm < 2; tm++) ldsm_x4(a[tm], a_base[tm] + ks * 32);
            #pragma unroll
            for (int np = 0; np < 2; np++) ldsm_x4(b[np], bb + b_off[np] + ks * 32);
            #pragma unroll
            for (int tm = 0; tm < 2; tm++)
                #pragma unroll
                for (int tn = 0; tn < 4; tn++)
                    mma_f16(acc[tm][tn], a[tm],
                            b[tn >> 1][(tn & 1) * 2], b[tn >> 1][(tn & 1) * 2 + 1]);
        }

        __syncthreads();
        if (c + 2 < 4) {
            cpchunk(c + 2, Bs[c & 1]);
            asm volatile("cp.async.commit_group;\n" ::: "memory");
        }

        #pragma unroll
        for (int tm = 0; tm < 2; tm++) {
            long r0 = rowBase + wm * 32 + tm * 16 + (lane >> 2);
            long r1 = r0 + 8;
            int colBase = c * 64 + wn * 32 + (lane & 3) * 2;
            #pragma unroll
            for (int tn = 0; tn < 4; tn++) {
                int col = colBase + tn * 8;
                float bx = 0.f, by = 0.f;
                if (col >= 128) {
                    float2 bv = *reinterpret_cast<const float2*>(b1 + col - 128);
                    bx = bv.x; by = bv.y;
                }
                if (r0 < n) {
                    __half2 v = __floats2half2_rn(acc[tm][tn][0] + bx,
                                                  acc[tm][tn][1] + by);
                    *reinterpret_cast<__half2*>(C + r0 * 256 + col) = v;
                }
                if (r1 < n) {
                    __half2 v = __floats2half2_rn(acc[tm][tn][2] + bx,
                                                  acc[tm][tn][3] + by);
                    *reinterpret_cast<__half2*>(C + r1 * 256 + col) = v;
                }
            }
        }

        if (c == 2) {
            asm volatile("cp.async.wait_group 0;\n" ::: "memory");
        } else if (c < 2) {
            asm volatile("cp.async.wait_group 1;\n" ::: "memory");
        }
        __syncthreads();
    }
}

// ---------------- edge decode v2: one warp = 4 edges, warp-wide row loads ----------------
// Each edge-row half (256B = 2 cache lines) is read by ONE LDG.64 warp
// instruction (32 lanes x 8B, contiguous) -> minimal within-LDG line replays.
// Lane i owns h-columns 4i..4i+3; w2 slice preloaded as float4.
__global__ void edge_v2(const int* __restrict__ e1, const int* __restrict__ e2,
                        const int* __restrict__ e3,
                        const float* __restrict__ w2, const float* __restrict__ b2,
                        float* __restrict__ out, int E) {
    const int tid = threadIdx.x;
    const int lane = tid & 31;
    const int w = (blockIdx.x * 256 + tid) >> 5;     // global warp id
    const int TE = 3 * E;
    const int e0 = w * 4;
    if (e0 >= TE) return;                            // E % 4 == 0

    // all 4 edges share a type (E divisible by 4)
    int t = (e0 >= 2 * E) ? 2 : (e0 >= E ? 1 : 0);
    int el = e0 - t * E;
    const int* idx = (t == 0) ? e1 : ((t == 1) ? e2 : e3);
    const __half* X = (t == 0) ? g_P : g_O;          // left proj (cols 0..127)
    const __half* Y = ((t == 1) ? g_P : g_O) + 128;  // right proj (cols 128..255)

    // index broadcast loads (all lanes same address -> 1 line each)
    int4 ss = *reinterpret_cast<const int4*>(idx + el);
    int4 dd = *reinterpret_cast<const int4*>(idx + el + E);
    const int sa[4] = { ss.x, ss.y, ss.z, ss.w };
    const int da[4] = { dd.x, dd.y, dd.z, dd.w };

    // 8 warp-wide LDG.64: each covers one 256B row-half (2 lines, contiguous)
    uint2 xv[4], yv[4];
    #pragma unroll
    for (int k = 0; k < 4; k++)
        xv[k] = __ldg(reinterpret_cast<const uint2*>(X + (size_t)sa[k] * 256) + lane);
    #pragma unroll
    for (int k = 0; k < 4; k++)
        yv[k] = __ldg(reinterpret_cast<const uint2*>(Y + (size_t)da[k] * 256) + lane);

    // per-lane weight slice: w2[4*lane .. 4*lane+3]
    const float4 w4 = *reinterpret_cast<const float4*>(w2 + lane * 4);
    const float bias = __ldg(b2);
    const __half2 z2 = __float2half2_rn(0.f);

    float sum[4];
    #pragma unroll
    for (int k = 0; k < 4; k++) {
        __half2 x0 = *reinterpret_cast<const __half2*>(&xv[k].x);
        __half2 x1 = *reinterpret_cast<const __half2*>(&xv[k].y);
        __half2 y0 = *reinterpret_cast<const __half2*>(&yv[k].x);
        __half2 y1 = *reinterpret_cast<const __half2*>(&yv[k].y);
        float2 r0 = __half22float2(__hmax2(__hadd2(x0, y0), z2));
        float2 r1 = __half22float2(__hmax2(__hadd2(x1, y1), z2));
        float s = fmaf(r0.x, w4.x, fmaf(r0.y, w4.y,
                  fmaf(r1.x, w4.z, r1.y * w4.w)));
        sum[k] = s;
    }

    // 4 independent 5-stage butterfly reduces
    #pragma unroll
    for (int o = 16; o > 0; o >>= 1) {
        #pragma unroll
        for (int k = 0; k < 4; k++)
            sum[k] += __shfl_xor_sync(0xffffffffu, sum[k], o);
    }

    if (lane == 0) out[e0]     = sum[0] + bias;
    if (lane == 1) out[e0 + 1] = sum[1] + bias;
    if (lane == 2) out[e0 + 2] = sum[2] + bias;
    if (lane == 3) out[e0 + 3] = sum[3] + bias;
}

extern "C" void kernel_launch(void* const* d_in, const int* in_sizes, int n_in,
                              void* d_out, int out_size) {
    const float* z_p = (const float*)d_in[0];
    const float* z_o = (const float*)d_in[1];
    const int*   e1  = (const int*)d_in[2];   // ptnp:  pnode src, onode dst
    const int*   e2  = (const int*)d_in[3];   // nptp:  onode src, pnode dst
    const int*   e3  = (const int*)d_in[4];   // nptnp: onode src, onode dst
    const float* w1  = (const float*)d_in[5];
    const float* b1  = (const float*)d_in[6];
    const float* w2  = (const float*)d_in[7];
    const float* b2  = (const float*)d_in[8];
    float* out = (float*)d_out;

    const int n = in_sizes[0] / HH;       // 100000
    const int E = in_sizes[2] / 2;        // 500000
    (void)n_in; (void)out_size;

    const int smemBytes = (128 * KS2 + 2 * 64 * KS2) * 2;   // 69632 B
    cudaFuncSetAttribute(gemm_mma, cudaFuncAttributeMaxDynamicSharedMemorySize,
                         smemBytes);

    prep_B<<<(256 * 128 + 255) / 256, 256>>>(w1);

    dim3 g((n + 127) / 128, 2);
    gemm_mma<<<g, 256, smemBytes>>>(z_p, z_o, b1, n);

    // one warp per 4 edges
    int warps = (3 * E + 3) / 4;
    int blocks = (warps * 32 + 255) / 256;
    edge_v2<<<blocks, 256>>>(e1, e2, e3, w2, b2, out, E);
}